// round 2
// baseline (speedup 1.0000x reference)
#include <cuda_runtime.h>
#include <math.h>

#define T_STEPS 512
#define BATCH   64
#define DIN     1024
#define HDIM    1024
#define TB      (T_STEPS * BATCH)   // 32768
#define HB      (BATCH * HDIM)      // 65536
#define NBLK    128

// ---------------- scratch (device globals; no allocation allowed) ----------------
__device__ float g_Xr[(size_t)TB * HDIM];   // 128MB: X@W_xr + b_r
__device__ float g_Xz[(size_t)TB * HDIM];
__device__ float g_Xh[(size_t)TB * HDIM];
__device__ float g_h0[HB];                  // initial state, row-major [64][1024]
__device__ float g_hT[HB];                  // h transposed [1024][64]
__device__ float g_RhT[HB];                 // (R*h) transposed [1024][64]
__device__ unsigned g_bar_cnt;
__device__ unsigned g_bar_gen;

// ---------------- init: copy state into h0 and hT ----------------
__global__ void init_h(const float* __restrict__ state) {
    int i = blockIdx.x * blockDim.x + threadIdx.x;
    if (i < HB) {
        int r = i >> 10, c = i & 1023;
        float v = state[i];
        g_h0[i] = v;
        g_hT[c * 64 + r] = v;
    }
}

// ---------------- precompute SGEMM: C = A[32768x1024] @ W[1024x1024] + bias ----------------
// tile 128x128, 256 threads, 8x8 micro (strided {c, 64+c} -> conflict-free LDS.128)
__global__ __launch_bounds__(256) void sgemm_xw(
    const float* __restrict__ A, const float* __restrict__ W,
    const float* __restrict__ bias, int which)
{
    float* C = (which == 0) ? g_Xr : (which == 1) ? g_Xz : g_Xh;

    __shared__ float As[8][128];
    __shared__ float Bs[8][128];

    int tid = threadIdx.x;
    int bx = blockIdx.x;   // N tile (0..7)
    int by = blockIdx.y;   // M tile (0..255)
    int tx = tid & 15, ty = tid >> 4;

    const float* Ap = A + (size_t)(by * 128 + (tid >> 1)) * 1024 + ((tid & 1) << 2);
    const float* Bp = W + (size_t)(tid >> 5) * 1024 + bx * 128 + ((tid & 31) << 2);

    float acc[8][8];
#pragma unroll
    for (int i = 0; i < 8; i++)
#pragma unroll
        for (int j = 0; j < 8; j++) acc[i][j] = 0.0f;

    for (int k0 = 0; k0 < 1024; k0 += 8) {
        float4 av = *(const float4*)(Ap + k0);
        float4 bv = *(const float4*)(Bp + (size_t)k0 * 1024);
        __syncthreads();
        int ar = (tid & 1) << 2, am = tid >> 1;
        As[ar + 0][am] = av.x;
        As[ar + 1][am] = av.y;
        As[ar + 2][am] = av.z;
        As[ar + 3][am] = av.w;
        *(float4*)&Bs[tid >> 5][(tid & 31) << 2] = bv;
        __syncthreads();
#pragma unroll
        for (int kk = 0; kk < 8; kk++) {
            float4 a0 = *(float4*)&As[kk][ty * 4];
            float4 a1 = *(float4*)&As[kk][64 + ty * 4];
            float4 b0 = *(float4*)&Bs[kk][tx * 4];
            float4 b1 = *(float4*)&Bs[kk][64 + tx * 4];
            float a[8] = {a0.x, a0.y, a0.z, a0.w, a1.x, a1.y, a1.z, a1.w};
            float b[8] = {b0.x, b0.y, b0.z, b0.w, b1.x, b1.y, b1.z, b1.w};
#pragma unroll
            for (int ri = 0; ri < 8; ri++)
#pragma unroll
                for (int cj = 0; cj < 8; cj++)
                    acc[ri][cj] = fmaf(a[ri], b[cj], acc[ri][cj]);
        }
    }

    float4 bias0 = *(const float4*)&bias[bx * 128 + tx * 4];
    float4 bias1 = *(const float4*)&bias[bx * 128 + 64 + tx * 4];
#pragma unroll
    for (int ri = 0; ri < 8; ri++) {
        int row_l = (ri < 4) ? (ty * 4 + ri) : (64 + ty * 4 + (ri - 4));
        size_t base = (size_t)(by * 128 + row_l) * 1024 + bx * 128;
        float4 o0 = make_float4(acc[ri][0] + bias0.x, acc[ri][1] + bias0.y,
                                acc[ri][2] + bias0.z, acc[ri][3] + bias0.w);
        float4 o1 = make_float4(acc[ri][4] + bias1.x, acc[ri][5] + bias1.y,
                                acc[ri][6] + bias1.z, acc[ri][7] + bias1.w);
        *(float4*)&C[base + tx * 4]      = o0;
        *(float4*)&C[base + 64 + tx * 4] = o1;
    }
}

// ---------------- software grid barrier (all NBLK blocks resident) ----------------
__device__ __forceinline__ void grid_barrier() {
    __threadfence();
    __syncthreads();
    if (threadIdx.x == 0) {
        volatile unsigned* vgen = (volatile unsigned*)&g_bar_gen;
        unsigned gen = *vgen;
        unsigned ticket = atomicAdd(&g_bar_cnt, 1u);
        if (ticket == NBLK - 1) {
            g_bar_cnt = 0;
            __threadfence();
            *vgen = gen + 1;
        } else {
            while (*vgen == gen) { }
        }
    }
    __syncthreads();
}

// ---------------- persistent recurrence kernel ----------------
// 128 blocks x 256 threads. Block b owns h-columns [b*8, b*8+8).
// Shared layout (floats):
//   wA [1024][16] : cols of W_hr (0..7) | W_hz (8..15)    @ 0      (64KB)
//   wB [1024][8]  : cols of W_hh                           @ 16384 (32KB)
//   hs [128][64]  : staged hT/RhT chunk                    @ 24576 (32KB)
//   red[256*68]   : cross-kgroup reduction                 @ 32768 (68KB)
//   zs [8][64]    : Z gate tile (survives across barrier)  @ 50176 (2KB)
#define SM_WA  0
#define SM_WB  16384
#define SM_HS  24576
#define SM_RED 32768
#define SM_ZS  50176
#define SM_FLOATS 50688
#define SM_BYTES  (SM_FLOATS * 4)

__global__ __launch_bounds__(256, 1) void gru_recurrence(
    const float* __restrict__ Whr, const float* __restrict__ Whz,
    const float* __restrict__ Whh, float* __restrict__ out)
{
    extern __shared__ float smem[];
    float* wA  = smem + SM_WA;
    float* wB  = smem + SM_WB;
    float* hs  = smem + SM_HS;
    float* red = smem + SM_RED;
    float* zs  = smem + SM_ZS;

    const int tid = threadIdx.x;
    const int cb  = blockIdx.x * 8;

    // ---- stage this block's weight columns into shared (once) ----
    for (int k = tid; k < 1024; k += 256) {
        size_t off = (size_t)k * 1024 + cb;
        *(float4*)&wA[k * 16 + 0]  = *(const float4*)(Whr + off);
        *(float4*)&wA[k * 16 + 4]  = *(const float4*)(Whr + off + 4);
        *(float4*)&wA[k * 16 + 8]  = *(const float4*)(Whz + off);
        *(float4*)&wA[k * 16 + 12] = *(const float4*)(Whz + off + 4);
        *(float4*)&wB[k * 8 + 0]   = *(const float4*)(Whh + off);
        *(float4*)&wB[k * 8 + 4]   = *(const float4*)(Whh + off + 4);
    }
    __syncthreads();

    // phase A thread coords: 16 k-groups x (2 col-halves x 8 row-threads)
    const int kgA = tid >> 4;          // 0..15
    const int ctA = (tid >> 3) & 1;    // 0..1
    const int mtA = tid & 7;           // 0..7
    // phase B thread coords: 32 k-groups x 8 row-threads
    const int kgB = tid >> 3;          // 0..31
    const int mtB = tid & 7;           // 0..7

#pragma unroll 1
    for (int t = 0; t < T_STEPS; t++) {
        const float* h_cur = (t == 0) ? g_h0 : (out + (size_t)(t - 1) * HB);
        const float* Xr_t = g_Xr + (size_t)t * HB;
        const float* Xz_t = g_Xz + (size_t)t * HB;
        const float* Xh_t = g_Xh + (size_t)t * HB;

        // ================= Phase A: pre_r / pre_z = h @ [W_hr|W_hz] cols =================
        {
            float acc[8][8];
#pragma unroll
            for (int i = 0; i < 8; i++)
#pragma unroll
                for (int j = 0; j < 8; j++) acc[i][j] = 0.0f;

#pragma unroll 1
            for (int c0 = 0; c0 < 1024; c0 += 128) {
                __syncthreads();
#pragma unroll
                for (int it = 0; it < 8; it++) {
                    int i = tid + it * 256;
                    int lk = i >> 4;
                    int rq = (i & 15) << 2;
                    *(float4*)&hs[lk * 64 + rq] =
                        __ldcg((const float4*)(g_hT + ((c0 + lk) << 6) + rq));
                }
                __syncthreads();
#pragma unroll
                for (int kk = 0; kk < 8; kk++) {
                    int lk = kgA * 8 + kk;
                    int gk = c0 + lk;
                    float4 a0 = *(float4*)&hs[lk * 64 + mtA * 4];
                    float4 a1 = *(float4*)&hs[lk * 64 + 32 + mtA * 4];
                    float4 b0 = *(float4*)&wA[gk * 16 + ctA * 8];
                    float4 b1 = *(float4*)&wA[gk * 16 + ctA * 8 + 4];
                    float a[8] = {a0.x, a0.y, a0.z, a0.w, a1.x, a1.y, a1.z, a1.w};
                    float b[8] = {b0.x, b0.y, b0.z, b0.w, b1.x, b1.y, b1.z, b1.w};
#pragma unroll
                    for (int ri = 0; ri < 8; ri++)
#pragma unroll
                        for (int cj = 0; cj < 8; cj++)
                            acc[ri][cj] = fmaf(a[ri], b[cj], acc[ri][cj]);
                }
            }
            // dump partials
            __syncthreads();
            {
                int slot = kgA * 16 + ctA * 8 + mtA;
                float* mr = red + slot * 68;
#pragma unroll
                for (int ri = 0; ri < 8; ri++) {
                    *(float4*)&mr[ri * 8]     = make_float4(acc[ri][0], acc[ri][1], acc[ri][2], acc[ri][3]);
                    *(float4*)&mr[ri * 8 + 4] = make_float4(acc[ri][4], acc[ri][5], acc[ri][6], acc[ri][7]);
                }
            }
            __syncthreads();
            // reduce across k-groups + activations
#pragma unroll
            for (int j = 0; j < 4; j++) {
                int oidx = tid + j * 256;       // 0..1023
                int r  = oidx & 63;
                int cg = oidx >> 6;             // 0..15
                int ctv = cg >> 3, cjv = cg & 7;
                int mtv = (r & 31) >> 2;
                int riv = (r & 3) + ((r >> 5) << 2);
                float s = 0.0f;
#pragma unroll
                for (int kg = 0; kg < 16; kg++)
                    s += red[(kg * 16 + ctv * 8 + mtv) * 68 + riv * 8 + cjv];
                if (cg < 8) {
                    int col = cb + cg;
                    float pre = s + Xr_t[r * 1024 + col];
                    float R = 1.0f / (1.0f + __expf(-pre));
                    float hv = __ldcg(&h_cur[r * 1024 + col]);
                    g_RhT[col * 64 + r] = R * hv;
                } else {
                    int col = cb + (cg - 8);
                    float pre = s + Xz_t[r * 1024 + col];
                    zs[(cg - 8) * 64 + r] = 1.0f / (1.0f + __expf(-pre));
                }
            }
        }
        grid_barrier();

        // ================= Phase B: Hh = tanh(Xh + (R*h) @ W_hh cols); gate update ==========
        {
            float acc[8][8];
#pragma unroll
            for (int i = 0; i < 8; i++)
#pragma unroll
                for (int j = 0; j < 8; j++) acc[i][j] = 0.0f;

#pragma unroll 1
            for (int c0 = 0; c0 < 1024; c0 += 128) {
                __syncthreads();
#pragma unroll
                for (int it = 0; it < 8; it++) {
                    int i = tid + it * 256;
                    int lk = i >> 4;
                    int rq = (i & 15) << 2;
                    *(float4*)&hs[lk * 64 + rq] =
                        __ldcg((const float4*)(g_RhT + ((c0 + lk) << 6) + rq));
                }
                __syncthreads();
#pragma unroll
                for (int kk = 0; kk < 4; kk++) {
                    int lk = kgB * 4 + kk;
                    int gk = c0 + lk;
                    float4 a0 = *(float4*)&hs[lk * 64 + mtB * 4];
                    float4 a1 = *(float4*)&hs[lk * 64 + 32 + mtB * 4];
                    float4 b0 = *(float4*)&wB[gk * 8];
                    float4 b1 = *(float4*)&wB[gk * 8 + 4];
                    float a[8] = {a0.x, a0.y, a0.z, a0.w, a1.x, a1.y, a1.z, a1.w};
                    float b[8] = {b0.x, b0.y, b0.z, b0.w, b1.x, b1.y, b1.z, b1.w};
#pragma unroll
                    for (int ri = 0; ri < 8; ri++)
#pragma unroll
                        for (int cj = 0; cj < 8; cj++)
                            acc[ri][cj] = fmaf(a[ri], b[cj], acc[ri][cj]);
                }
            }
            __syncthreads();
            {
                int slot = kgB * 8 + mtB;
                float* mr = red + slot * 68;
#pragma unroll
                for (int ri = 0; ri < 8; ri++) {
                    *(float4*)&mr[ri * 8]     = make_float4(acc[ri][0], acc[ri][1], acc[ri][2], acc[ri][3]);
                    *(float4*)&mr[ri * 8 + 4] = make_float4(acc[ri][4], acc[ri][5], acc[ri][6], acc[ri][7]);
                }
            }
            __syncthreads();
            float* out_t = out + (size_t)t * HB;
#pragma unroll
            for (int j = 0; j < 2; j++) {
                int oidx = tid + j * 256;      // 0..511
                int r = oidx & 63;
                int c = oidx >> 6;             // 0..7
                int mtv = (r & 31) >> 2;
                int riv = (r & 3) + ((r >> 5) << 2);
                float s = 0.0f;
#pragma unroll
                for (int kg = 0; kg < 32; kg++)
                    s += red[(kg * 8 + mtv) * 68 + riv * 8 + c];
                int col = cb + c;
                float Hh = tanhf(s + Xh_t[r * 1024 + col]);
                float Z  = zs[c * 64 + r];
                float hv = __ldcg(&h_cur[r * 1024 + col]);
                float hn = Z * hv + (1.0f - Z) * Hh;
                out_t[r * 1024 + col] = hn;
                g_hT[col * 64 + r] = hn;
                if (t == T_STEPS - 1)
                    out[(size_t)T_STEPS * HB + r * 1024 + col] = hn;  // final_state
            }
        }
        grid_barrier();
    }
}

// ---------------- launch ----------------
extern "C" void kernel_launch(void* const* d_in, const int* in_sizes, int n_in,
                              void* d_out, int out_size) {
    const float* X     = (const float*)d_in[0];
    const float* state = (const float*)d_in[1];
    const float* W_xr  = (const float*)d_in[2];
    const float* W_hr  = (const float*)d_in[3];
    const float* b_r   = (const float*)d_in[4];
    const float* W_xz  = (const float*)d_in[5];
    const float* W_hz  = (const float*)d_in[6];
    const float* b_z   = (const float*)d_in[7];
    const float* W_xh  = (const float*)d_in[8];
    const float* W_hh  = (const float*)d_in[9];
    const float* b_h   = (const float*)d_in[10];
    float* out = (float*)d_out;

    init_h<<<HB / 256, 256>>>(state);

    dim3 g(8, 256);
    sgemm_xw<<<g, 256>>>(X, W_xr, b_r, 0);
    sgemm_xw<<<g, 256>>>(X, W_xz, b_z, 1);
    sgemm_xw<<<g, 256>>>(X, W_xh, b_h, 2);

    cudaFuncSetAttribute(gru_recurrence,
                         cudaFuncAttributeMaxDynamicSharedMemorySize, SM_BYTES);
    gru_recurrence<<<NBLK, 256, SM_BYTES>>>(W_hr, W_hz, W_hh, out);
}

// round 5
// speedup vs baseline: 1.1637x; 1.1637x over previous
#include <cuda_runtime.h>
#include <cuda_bf16.h>
#include <cstdint>
#include <math.h>

#define T_STEPS 512
#define BATCH   64
#define DIN     1024
#define HDIM    1024
#define TB      (T_STEPS * BATCH)   // 32768
#define HB      (BATCH * HDIM)      // 65536
#define NBLK    128

// ---------------- scratch (device globals; no allocation allowed) ----------------
__device__ float g_Xr[(size_t)TB * HDIM];
__device__ float g_Xz[(size_t)TB * HDIM];
__device__ float g_Xh[(size_t)TB * HDIM];
__device__ __nv_bfloat16 g_Xhi[(size_t)TB * DIN];        // X split hi
__device__ __nv_bfloat16 g_Xlo[(size_t)TB * DIN];        // X split lo
__device__ __nv_bfloat16 g_Wthi[(size_t)3 * HDIM * DIN]; // W^T split hi [3*1024][1024]
__device__ __nv_bfloat16 g_Wtlo[(size_t)3 * HDIM * DIN];
__device__ float g_h0[HB];
__device__ float g_hT[HB];
__device__ float g_RhT[HB];
__device__ unsigned g_bar_cnt;
__device__ unsigned g_bar_gen;

// ---------------- PTX helpers (baseline PTX only — no 'a'-gated instructions) ----------------
__device__ __forceinline__ uint32_t smem_u32(const void* p) {
    uint32_t a;
    asm("{ .reg .u64 t; cvta.to.shared.u64 t, %1; cvt.u32.u64 %0, t; }" : "=r"(a) : "l"(p));
    return a;
}
#define CP_ASYNC16(dst, src) \
    asm volatile("cp.async.cg.shared.global [%0], [%1], 16;" :: "r"(dst), "l"(src))
#define CP_COMMIT() asm volatile("cp.async.commit_group;" ::: "memory")
#define CP_WAIT(n)  asm volatile("cp.async.wait_group %0;" :: "n"(n) : "memory")

#define LDSM_X4(r, a) \
    asm volatile("ldmatrix.sync.aligned.m8n8.x4.shared.b16 {%0,%1,%2,%3}, [%4];" \
        : "=r"((r)[0]), "=r"((r)[1]), "=r"((r)[2]), "=r"((r)[3]) : "r"(a))

#define MMA16816(d, a, b0v, b1v) \
    asm volatile("mma.sync.aligned.m16n8k16.row.col.f32.bf16.bf16.f32 " \
        "{%0,%1,%2,%3}, {%4,%5,%6,%7}, {%8,%9}, {%0,%1,%2,%3};" \
        : "+f"((d)[0]), "+f"((d)[1]), "+f"((d)[2]), "+f"((d)[3]) \
        : "r"((a)[0]), "r"((a)[1]), "r"((a)[2]), "r"((a)[3]), "r"(b0v), "r"(b1v))

// packed fp32x2 FMA (FFMA2 path: 2x fp32 throughput) — compiles for plain sm_103
#define PACKDUP(d, f) asm("mov.b64 %0, {%1, %1};" : "=l"(d) : "r"(__float_as_uint(f)))
#define FMA2(d, a, b) asm("fma.rn.f32x2 %0, %1, %2, %0;" : "+l"(d) : "l"(a), "l"(b))
#define UNPK2(lo, hi, v) do { unsigned _l, _h; \
    asm("mov.b64 {%0, %1}, %2;" : "=r"(_l), "=r"(_h) : "l"(v)); \
    lo = __uint_as_float(_l); hi = __uint_as_float(_h); } while (0)

// ---------------- init ----------------
__global__ void init_h(const float* __restrict__ state) {
    int i = blockIdx.x * blockDim.x + threadIdx.x;
    if (i < HB) {
        int r = i >> 10, c = i & 1023;
        float v = state[i];
        g_h0[i] = v;
        g_hT[c * 64 + r] = v;
    }
}

// ---------------- X -> bf16 hi/lo split ----------------
__global__ __launch_bounds__(256) void conv_X(const float* __restrict__ X) {
    size_t i = (size_t)blockIdx.x * 256 + threadIdx.x;   // float4 index
    float4 v = ((const float4*)X)[i];
    __nv_bfloat16 h0 = __float2bfloat16(v.x), h1 = __float2bfloat16(v.y);
    __nv_bfloat16 h2 = __float2bfloat16(v.z), h3 = __float2bfloat16(v.w);
    __nv_bfloat16 l0 = __float2bfloat16(v.x - __bfloat162float(h0));
    __nv_bfloat16 l1 = __float2bfloat16(v.y - __bfloat162float(h1));
    __nv_bfloat16 l2 = __float2bfloat16(v.z - __bfloat162float(h2));
    __nv_bfloat16 l3 = __float2bfloat16(v.w - __bfloat162float(h3));
    uint2 ph, pl;
    ph.x = (uint32_t)__bfloat16_as_ushort(h0) | ((uint32_t)__bfloat16_as_ushort(h1) << 16);
    ph.y = (uint32_t)__bfloat16_as_ushort(h2) | ((uint32_t)__bfloat16_as_ushort(h3) << 16);
    pl.x = (uint32_t)__bfloat16_as_ushort(l0) | ((uint32_t)__bfloat16_as_ushort(l1) << 16);
    pl.y = (uint32_t)__bfloat16_as_ushort(l2) | ((uint32_t)__bfloat16_as_ushort(l3) << 16);
    ((uint2*)g_Xhi)[i] = ph;
    ((uint2*)g_Xlo)[i] = pl;
}

// ---------------- W -> transposed bf16 hi/lo split ----------------
__global__ void conv_W(const float* __restrict__ W0, const float* __restrict__ W1,
                       const float* __restrict__ W2) {
    __shared__ float tile[32][33];
    int mat = blockIdx.z;
    const float* W = (mat == 0) ? W0 : (mat == 1) ? W1 : W2;
    int k0 = blockIdx.y * 32, n0 = blockIdx.x * 32;
    for (int i = threadIdx.y; i < 32; i += 8)
        tile[i][threadIdx.x] = W[(size_t)(k0 + i) * 1024 + n0 + threadIdx.x];
    __syncthreads();
    size_t mbase = (size_t)mat * 1024 * 1024;
    for (int i = threadIdx.y; i < 32; i += 8) {
        float v = tile[threadIdx.x][i];   // W[k0+tx][n0+i]
        __nv_bfloat16 hv = __float2bfloat16(v);
        __nv_bfloat16 lv = __float2bfloat16(v - __bfloat162float(hv));
        size_t off = mbase + (size_t)(n0 + i) * 1024 + k0 + threadIdx.x;
        g_Wthi[off] = hv;
        g_Wtlo[off] = lv;
    }
}

// ---------------- mma.sync precompute GEMM ----------------
// C[32768 x 3072] = Xsplit @ Wt^T via 3-term bf16 split.
// Block tile 128x128, 8 warps (2 M x 4 N), warp tile 64x32, K-chunks of 32,
// cp.async double buffer. SMEM rows padded to 80B (ldmatrix conflict-free).
#define MAT_BYTES 10240               // 128 rows * 80B
#define BUF_BYTES (4 * MAT_BYTES)     // Ahi | Alo | Bhi | Blo
#define PRE_SMEM  (2 * BUF_BYTES)     // 81920

__global__ __launch_bounds__(256, 1) void mma_precompute(
    const float* __restrict__ b_r, const float* __restrict__ b_z, const float* __restrict__ b_h)
{
    extern __shared__ char smem[];
    const uint32_t sb = smem_u32(smem);
    const int tid = threadIdx.x;
    const int wid = tid >> 5, lid = tid & 31;
    const int nt = blockIdx.x;   // 0..23  (gate*8 + ncol-tile)
    const int mt = blockIdx.y;   // 0..255

    const size_t arow0 = (size_t)mt * 128;
    const size_t brow0 = (size_t)nt * 128;

    // per-thread global load coords: i in 0..7; matrix = i>>1
    const int ldrow = (tid >> 2);          // 0..63 (plus (i&1)*64)
    const int ldseg = (tid & 3);           // 16B segment within 64B row

    float acc[4][4][4];
#pragma unroll
    for (int i = 0; i < 4; i++)
#pragma unroll
        for (int j = 0; j < 4; j++)
#pragma unroll
            for (int q = 0; q < 4; q++) acc[i][j][q] = 0.0f;

    // ldmatrix source addresses (within a buffer)
    const uint32_t a_off = (uint32_t)(((lid & 7) + ((lid >> 3) & 1) * 8) * 80 + (lid >> 4) * 16);
    const uint32_t b_off = (uint32_t)(((lid & 7) + (lid >> 4) * 8) * 80 + ((lid >> 3) & 1) * 16);
    const uint32_t awbase = sb + (wid & 1) * (64 * 80);
    const uint32_t bwbase = sb + 2 * MAT_BYTES + (wid >> 1) * (32 * 80);

#define PREFETCH(c, buf) do { \
    uint32_t sbase = sb + (buf) * BUF_BYTES; \
    const __nv_bfloat16* g0 = g_Xhi  + (arow0) * 1024 + (c) * 32; \
    const __nv_bfloat16* g1 = g_Xlo  + (arow0) * 1024 + (c) * 32; \
    const __nv_bfloat16* g2 = g_Wthi + (brow0) * 1024 + (c) * 32; \
    const __nv_bfloat16* g3 = g_Wtlo + (brow0) * 1024 + (c) * 32; \
    const __nv_bfloat16* gs[4] = {g0, g1, g2, g3}; \
    _Pragma("unroll") \
    for (int i = 0; i < 8; i++) { \
        int m = i >> 1; \
        int row = (i & 1) * 64 + ldrow; \
        uint32_t dst = sbase + m * MAT_BYTES + row * 80 + ldseg * 16; \
        CP_ASYNC16(dst, gs[m] + (size_t)row * 1024 + ldseg * 8); \
    } \
    CP_COMMIT(); \
} while (0)

    PREFETCH(0, 0);

#pragma unroll 1
    for (int c = 0; c < 32; c++) {
        int buf = c & 1;
        if (c + 1 < 32) { PREFETCH(c + 1, buf ^ 1); CP_WAIT(1); }
        else            { CP_WAIT(0); }
        __syncthreads();

        uint32_t ab = awbase + buf * BUF_BYTES;
        uint32_t bb = bwbase + buf * BUF_BYTES;
#pragma unroll
        for (int ks = 0; ks < 2; ks++) {
            uint32_t akb = ab + ks * 32 + a_off;
            uint32_t bkb = bb + ks * 32 + b_off;
            uint32_t ah[4][4], bhv[2][4], blv[2][4];
#pragma unroll
            for (int i = 0; i < 4; i++) LDSM_X4(ah[i], akb + i * (16 * 80));
#pragma unroll
            for (int p = 0; p < 2; p++) {
                LDSM_X4(bhv[p], bkb + p * (16 * 80));
                LDSM_X4(blv[p], bkb + MAT_BYTES + p * (16 * 80));
            }
            // acc += Ahi*Bhi + Ahi*Blo
#pragma unroll
            for (int i = 0; i < 4; i++)
#pragma unroll
                for (int j = 0; j < 4; j++) {
                    MMA16816(acc[i][j], ah[i], bhv[j >> 1][(j & 1) * 2], bhv[j >> 1][(j & 1) * 2 + 1]);
                    MMA16816(acc[i][j], ah[i], blv[j >> 1][(j & 1) * 2], blv[j >> 1][(j & 1) * 2 + 1]);
                }
            // reload ah <- Alo; acc += Alo*Bhi
#pragma unroll
            for (int i = 0; i < 4; i++) LDSM_X4(ah[i], akb + MAT_BYTES + i * (16 * 80));
#pragma unroll
            for (int i = 0; i < 4; i++)
#pragma unroll
                for (int j = 0; j < 4; j++)
                    MMA16816(acc[i][j], ah[i], bhv[j >> 1][(j & 1) * 2], bhv[j >> 1][(j & 1) * 2 + 1]);
        }
        __syncthreads();
    }
#undef PREFETCH

    // epilogue: direct global writes + bias
    const int gate = nt >> 3;
    const float* bias = (gate == 0) ? b_r : (gate == 1) ? b_z : b_h;
    float* Cout = (gate == 0) ? g_Xr : (gate == 1) ? g_Xz : g_Xh;
    const int mrow0 = mt * 128 + (wid & 1) * 64;
    const int ncol0 = (nt & 7) * 128 + (wid >> 1) * 32;
#pragma unroll
    for (int i = 0; i < 4; i++) {
        int row = mrow0 + i * 16 + (lid >> 2);
#pragma unroll
        for (int j = 0; j < 4; j++) {
            int col = ncol0 + j * 8 + (lid & 3) * 2;
            float2 b2 = *(const float2*)&bias[col];
            float2 v0 = make_float2(acc[i][j][0] + b2.x, acc[i][j][1] + b2.y);
            float2 v1 = make_float2(acc[i][j][2] + b2.x, acc[i][j][3] + b2.y);
            *(float2*)&Cout[(size_t)row * 1024 + col]       = v0;
            *(float2*)&Cout[(size_t)(row + 8) * 1024 + col] = v1;
        }
    }
}

// ---------------- software grid barrier ----------------
__device__ __forceinline__ void grid_barrier() {
    __threadfence();
    __syncthreads();
    if (threadIdx.x == 0) {
        volatile unsigned* vgen = (volatile unsigned*)&g_bar_gen;
        unsigned gen = *vgen;
        unsigned ticket = atomicAdd(&g_bar_cnt, 1u);
        if (ticket == NBLK - 1) {
            g_bar_cnt = 0;
            __threadfence();
            *vgen = gen + 1;
        } else {
            while (*vgen == gen) { }
        }
    }
    __syncthreads();
}

// ---------------- persistent recurrence kernel (FFMA2 inner product) ----------------
#define SM_WA  0
#define SM_WB  16384
#define SM_HS  24576
#define SM_RED 32768
#define SM_ZS  50176
#define SM_FLOATS 50688
#define SM_BYTES  (SM_FLOATS * 4)

__global__ __launch_bounds__(256, 1) void gru_recurrence(
    const float* __restrict__ Whr, const float* __restrict__ Whz,
    const float* __restrict__ Whh, float* __restrict__ out)
{
    extern __shared__ float smemf[];
    float* wA  = smemf + SM_WA;
    float* wB  = smemf + SM_WB;
    float* hs  = smemf + SM_HS;
    float* red = smemf + SM_RED;
    float* zs  = smemf + SM_ZS;

    const int tid = threadIdx.x;
    const int cb  = blockIdx.x * 8;

    for (int k = tid; k < 1024; k += 256) {
        size_t off = (size_t)k * 1024 + cb;
        *(float4*)&wA[k * 16 + 0]  = *(const float4*)(Whr + off);
        *(float4*)&wA[k * 16 + 4]  = *(const float4*)(Whr + off + 4);
        *(float4*)&wA[k * 16 + 8]  = *(const float4*)(Whz + off);
        *(float4*)&wA[k * 16 + 12] = *(const float4*)(Whz + off + 4);
        *(float4*)&wB[k * 8 + 0]   = *(const float4*)(Whh + off);
        *(float4*)&wB[k * 8 + 4]   = *(const float4*)(Whh + off + 4);
    }
    __syncthreads();

    const int kgA = tid >> 4;
    const int ctA = (tid >> 3) & 1;
    const int mtA = tid & 7;
    const int kgB = tid >> 3;
    const int mtB = tid & 7;

#pragma unroll 1
    for (int t = 0; t < T_STEPS; t++) {
        const float* h_cur = (t == 0) ? g_h0 : (out + (size_t)(t - 1) * HB);
        const float* Xr_t = g_Xr + (size_t)t * HB;
        const float* Xz_t = g_Xz + (size_t)t * HB;
        const float* Xh_t = g_Xh + (size_t)t * HB;

        // ============ Phase A ============
        {
            unsigned long long accp[8][4];
#pragma unroll
            for (int i = 0; i < 8; i++)
#pragma unroll
                for (int j = 0; j < 4; j++) accp[i][j] = 0ull;

#pragma unroll 1
            for (int c0 = 0; c0 < 1024; c0 += 128) {
                __syncthreads();
#pragma unroll
                for (int it = 0; it < 8; it++) {
                    int i = tid + it * 256;
                    int lk = i >> 4;
                    int rq = (i & 15) << 2;
                    *(float4*)&hs[lk * 64 + rq] =
                        __ldcg((const float4*)(g_hT + ((c0 + lk) << 6) + rq));
                }
                __syncthreads();
#pragma unroll
                for (int kk = 0; kk < 8; kk++) {
                    int lk = kgA * 8 + kk;
                    int gk = c0 + lk;
                    float4 a0 = *(float4*)&hs[lk * 64 + mtA * 4];
                    float4 a1 = *(float4*)&hs[lk * 64 + 32 + mtA * 4];
                    unsigned long long aa[8];
                    PACKDUP(aa[0], a0.x); PACKDUP(aa[1], a0.y);
                    PACKDUP(aa[2], a0.z); PACKDUP(aa[3], a0.w);
                    PACKDUP(aa[4], a1.x); PACKDUP(aa[5], a1.y);
                    PACKDUP(aa[6], a1.z); PACKDUP(aa[7], a1.w);
                    ulonglong2 b01 = *(ulonglong2*)&wA[gk * 16 + ctA * 8];
                    ulonglong2 b23 = *(ulonglong2*)&wA[gk * 16 + ctA * 8 + 4];
#pragma unroll
                    for (int ri = 0; ri < 8; ri++) {
                        FMA2(accp[ri][0], aa[ri], b01.x);
                        FMA2(accp[ri][1], aa[ri], b01.y);
                        FMA2(accp[ri][2], aa[ri], b23.x);
                        FMA2(accp[ri][3], aa[ri], b23.y);
                    }
                }
            }
            __syncthreads();
            {
                int slot = kgA * 16 + ctA * 8 + mtA;
                float* mr = red + slot * 68;
#pragma unroll
                for (int ri = 0; ri < 8; ri++) {
                    float ac[8];
                    UNPK2(ac[0], ac[1], accp[ri][0]);
                    UNPK2(ac[2], ac[3], accp[ri][1]);
                    UNPK2(ac[4], ac[5], accp[ri][2]);
                    UNPK2(ac[6], ac[7], accp[ri][3]);
                    *(float4*)&mr[ri * 8]     = make_float4(ac[0], ac[1], ac[2], ac[3]);
                    *(float4*)&mr[ri * 8 + 4] = make_float4(ac[4], ac[5], ac[6], ac[7]);
                }
            }
            __syncthreads();
#pragma unroll
            for (int j = 0; j < 4; j++) {
                int oidx = tid + j * 256;
                int r  = oidx & 63;
                int cg = oidx >> 6;
                int ctv = cg >> 3, cjv = cg & 7;
                int mtv = (r & 31) >> 2;
                int riv = (r & 3) + ((r >> 5) << 2);
                float s = 0.0f;
#pragma unroll
                for (int kg = 0; kg < 16; kg++)
                    s += red[(kg * 16 + ctv * 8 + mtv) * 68 + riv * 8 + cjv];
                if (cg < 8) {
                    int col = cb + cg;
                    float pre = s + Xr_t[r * 1024 + col];
                    float R = 1.0f / (1.0f + __expf(-pre));
                    float hv = __ldcg(&h_cur[r * 1024 + col]);
                    g_RhT[col * 64 + r] = R * hv;
                } else {
                    int col = cb + (cg - 8);
                    float pre = s + Xz_t[r * 1024 + col];
                    zs[(cg - 8) * 64 + r] = 1.0f / (1.0f + __expf(-pre));
                }
            }
        }
        grid_barrier();

        // ============ Phase B ============
        {
            unsigned long long accp[8][4];
#pragma unroll
            for (int i = 0; i < 8; i++)
#pragma unroll
                for (int j = 0; j < 4; j++) accp[i][j] = 0ull;

#pragma unroll 1
            for (int c0 = 0; c0 < 1024; c0 += 128) {
                __syncthreads();
#pragma unroll
                for (int it = 0; it < 8; it++) {
                    int i = tid + it * 256;
                    int lk = i >> 4;
                    int rq = (i & 15) << 2;
                    *(float4*)&hs[lk * 64 + rq] =
                        __ldcg((const float4*)(g_RhT + ((c0 + lk) << 6) + rq));
                }
                __syncthreads();
#pragma unroll
                for (int kk = 0; kk < 4; kk++) {
                    int lk = kgB * 4 + kk;
                    int gk = c0 + lk;
                    float4 a0 = *(float4*)&hs[lk * 64 + mtB * 4];
                    float4 a1 = *(float4*)&hs[lk * 64 + 32 + mtB * 4];
                    unsigned long long aa[8];
                    PACKDUP(aa[0], a0.x); PACKDUP(aa[1], a0.y);
                    PACKDUP(aa[2], a0.z); PACKDUP(aa[3], a0.w);
                    PACKDUP(aa[4], a1.x); PACKDUP(aa[5], a1.y);
                    PACKDUP(aa[6], a1.z); PACKDUP(aa[7], a1.w);
                    ulonglong2 b01 = *(ulonglong2*)&wB[gk * 8];
                    ulonglong2 b23 = *(ulonglong2*)&wB[gk * 8 + 4];
#pragma unroll
                    for (int ri = 0; ri < 8; ri++) {
                        FMA2(accp[ri][0], aa[ri], b01.x);
                        FMA2(accp[ri][1], aa[ri], b01.y);
                        FMA2(accp[ri][2], aa[ri], b23.x);
                        FMA2(accp[ri][3], aa[ri], b23.y);
                    }
                }
            }
            __syncthreads();
            {
                int slot = kgB * 8 + mtB;
                float* mr = red + slot * 68;
#pragma unroll
                for (int ri = 0; ri < 8; ri++) {
                    float ac[8];
                    UNPK2(ac[0], ac[1], accp[ri][0]);
                    UNPK2(ac[2], ac[3], accp[ri][1]);
                    UNPK2(ac[4], ac[5], accp[ri][2]);
                    UNPK2(ac[6], ac[7], accp[ri][3]);
                    *(float4*)&mr[ri * 8]     = make_float4(ac[0], ac[1], ac[2], ac[3]);
                    *(float4*)&mr[ri * 8 + 4] = make_float4(ac[4], ac[5], ac[6], ac[7]);
                }
            }
            __syncthreads();
            float* out_t = out + (size_t)t * HB;
#pragma unroll
            for (int j = 0; j < 2; j++) {
                int oidx = tid + j * 256;
                int r = oidx & 63;
                int c = oidx >> 6;
                int mtv = (r & 31) >> 2;
                int riv = (r & 3) + ((r >> 5) << 2);
                float s = 0.0f;
#pragma unroll
                for (int kg = 0; kg < 32; kg++)
                    s += red[(kg * 8 + mtv) * 68 + riv * 8 + c];
                int col = cb + c;
                float Hh = tanhf(s + Xh_t[r * 1024 + col]);
                float Z  = zs[c * 64 + r];
                float hv = __ldcg(&h_cur[r * 1024 + col]);
                float hn = Z * hv + (1.0f - Z) * Hh;
                out_t[r * 1024 + col] = hn;
                g_hT[col * 64 + r] = hn;
                if (t == T_STEPS - 1)
                    out[(size_t)T_STEPS * HB + r * 1024 + col] = hn;
            }
        }
        grid_barrier();
    }
}

// ---------------- launch ----------------
extern "C" void kernel_launch(void* const* d_in, const int* in_sizes, int n_in,
                              void* d_out, int out_size) {
    const float* X     = (const float*)d_in[0];
    const float* state = (const float*)d_in[1];
    const float* W_xr  = (const float*)d_in[2];
    const float* W_hr  = (const float*)d_in[3];
    const float* b_r   = (const float*)d_in[4];
    const float* W_xz  = (const float*)d_in[5];
    const float* W_hz  = (const float*)d_in[6];
    const float* b_z   = (const float*)d_in[7];
    const float* W_xh  = (const float*)d_in[8];
    const float* W_hh  = (const float*)d_in[9];
    const float* b_h   = (const float*)d_in[10];
    float* out = (float*)d_out;

    init_h<<<HB / 256, 256>>>(state);
    conv_X<<<(TB * DIN / 4) / 256, 256>>>(X);
    conv_W<<<dim3(32, 32, 3), dim3(32, 8)>>>(W_xr, W_xz, W_xh);

    cudaFuncSetAttribute(mma_precompute,
                         cudaFuncAttributeMaxDynamicSharedMemorySize, PRE_SMEM);
    cudaFuncSetAttribute(gru_recurrence,
                         cudaFuncAttributeMaxDynamicSharedMemorySize, SM_BYTES);

    mma_precompute<<<dim3(24, 256), 256, PRE_SMEM>>>(b_r, b_z, b_h);
    gru_recurrence<<<NBLK, 256, SM_BYTES>>>(W_hr, W_hz, W_hh, out);
}